// round 15
// baseline (speedup 1.0000x reference)
#include <cuda_runtime.h>
#include <math.h>
#include <cfloat>
#include <stdint.h>

// ---------------- problem constants ----------------
#define BB     2
#define NQ     2048
#define NK     2048
#define DIMM   512
#define HH     8
#define DH     64
#define INNER  512
#define NBANDS 32
#define DWP    577      // DIM + 2*NUM_BANDS + 1
#define TOPKK  64
#define MROWS  (BB*NQ)  // 4096

// ---------------- scratch (device globals; no cudaMalloc allowed) ----------------
__device__ float g_enc[NQ * 65];
__device__ float g_Aq[(size_t)MROWS * DWP];
__device__ float g_Ak[(size_t)MROWS * DWP];
__device__ float g_Q [(size_t)MROWS * INNER];
__device__ float g_K [(size_t)MROWS * INNER];
__device__ float g_V [(size_t)MROWS * INNER];
__device__ float g_O [(size_t)MROWS * INNER];

// ---------------- f32x2 packed helpers (sm_103a) ----------------
__device__ __forceinline__ unsigned long long pk2(float lo, float hi) {
    unsigned long long r;
    asm("mov.b64 %0, {%1, %2};" : "=l"(r) : "f"(lo), "f"(hi));
    return r;
}
__device__ __forceinline__ void upk2(unsigned long long v, float& lo, float& hi) {
    asm("mov.b64 {%0, %1}, %2;" : "=f"(lo), "=f"(hi) : "l"(v));
}
__device__ __forceinline__ unsigned long long fma2(unsigned long long a,
                                                   unsigned long long b,
                                                   unsigned long long c) {
    unsigned long long d;
    asm("fma.rn.f32x2 %0, %1, %2, %3;" : "=l"(d) : "l"(a), "l"(b), "l"(c));
    return d;
}

// ---------------- fourier encode ----------------
__global__ void enc_kernel() {
    int i = blockIdx.x * blockDim.x + threadIdx.x;
    if (i >= NQ) return;
    float step = 2.0f / 2047.0f;
    float pos = fmaf((float)i, step, -1.0f);
    g_enc[i * 65 + 64] = pos;
    #pragma unroll 4
    for (int b = 0; b < NBANDS; b++) {
        float sc = 1.0f + 29.0f * (float)b / 31.0f;   // linspace(1, 30, 32)
        float xs = (pos * sc) * 3.14159265358979323846f;
        g_enc[i * 65 + b]          = sinf(xs);
        g_enc[i * 65 + NBANDS + b] = cosf(xs);
    }
}

// ---------------- concat [x | enc] and [context | enc] ----------------
__global__ void concat_kernel(const float* __restrict__ x, const float* __restrict__ ctx) {
    int idx = blockIdx.x * blockDim.x + threadIdx.x;
    const int total = MROWS * DWP;
    if (idx >= total) return;
    int row = idx / DWP;
    int c   = idx - row * DWP;
    if (c < DIMM) {
        g_Aq[idx] = x  [(size_t)row * DIMM + c];
        g_Ak[idx] = ctx[(size_t)row * DIMM + c];
    } else {
        int i = row & (NQ - 1);
        float e = g_enc[i * 65 + (c - DIMM)];
        g_Aq[idx] = e;
        g_Ak[idx] = e;
    }
}

// ---------------- fp32 tiled GEMM with packed f32x2 FMA (round-10, verbatim) ----------------
__global__ __launch_bounds__(256) void gemm_bias(
    const float* __restrict__ A, int lda,
    const float* __restrict__ W,
    const float* __restrict__ bias,
    float* __restrict__ C,
    int M, int N, int K)
{
    __shared__ float As[16][132];
    __shared__ float Bs[16][64];

    int bm = blockIdx.y * 128;
    int bn = blockIdx.x * 64;
    int tid = threadIdx.x;
    int tx = tid & 15;
    int ty = tid >> 4;

    unsigned long long accP[4][2], accQ[4][2];
    #pragma unroll
    for (int ip = 0; ip < 4; ip++)
        #pragma unroll
        for (int jp = 0; jp < 2; jp++) { accP[ip][jp] = 0ull; accQ[ip][jp] = 0ull; }

    for (int k0 = 0; k0 < K; k0 += 16) {
        #pragma unroll
        for (int i = 0; i < 8; i++) {
            int e = tid + i * 256;
            int m = e >> 4, kk = e & 15;
            int gk = k0 + kk;
            As[kk][m] = (gk < K) ? A[(size_t)(bm + m) * lda + gk] : 0.0f;
        }
        {
            int kk = tid >> 4;
            int nc = (tid & 15) << 2;
            int gk = k0 + kk;
            float4 v = make_float4(0.f, 0.f, 0.f, 0.f);
            if (gk < K) v = *(const float4*)(W + (size_t)gk * N + bn + nc);
            *(float4*)&Bs[kk][nc] = v;
        }
        __syncthreads();
        #pragma unroll
        for (int kk = 0; kk < 16; kk++) {
            float4 a0 = *(const float4*)&As[kk][ty * 8];
            float4 a1 = *(const float4*)&As[kk][ty * 8 + 4];
            float4 bv = *(const float4*)&Bs[kk][tx * 4];
            unsigned long long ap[4];
            ap[0] = pk2(a0.x, a0.y);
            ap[1] = pk2(a0.z, a0.w);
            ap[2] = pk2(a1.x, a1.y);
            ap[3] = pk2(a1.z, a1.w);
            unsigned long long bP0 = pk2(bv.x, bv.y);
            unsigned long long bP1 = pk2(bv.z, bv.w);
            unsigned long long bQ0 = pk2(bv.y, bv.x);
            unsigned long long bQ1 = pk2(bv.w, bv.z);
            #pragma unroll
            for (int ip = 0; ip < 4; ip++) {
                accP[ip][0] = fma2(ap[ip], bP0, accP[ip][0]);
                accQ[ip][0] = fma2(ap[ip], bQ0, accQ[ip][0]);
                accP[ip][1] = fma2(ap[ip], bP1, accP[ip][1]);
                accQ[ip][1] = fma2(ap[ip], bQ1, accQ[ip][1]);
            }
        }
        __syncthreads();
    }

    float acc[8][4];
    #pragma unroll
    for (int ip = 0; ip < 4; ip++) {
        #pragma unroll
        for (int jp = 0; jp < 2; jp++) {
            float plo, phi, qlo, qhi;
            upk2(accP[ip][jp], plo, phi);
            upk2(accQ[ip][jp], qlo, qhi);
            acc[2 * ip][2 * jp]         = plo;
            acc[2 * ip + 1][2 * jp + 1] = phi;
            acc[2 * ip][2 * jp + 1]     = qlo;
            acc[2 * ip + 1][2 * jp]     = qhi;
        }
    }

    float4 bb = *(const float4*)(bias + bn + tx * 4);
    #pragma unroll
    for (int i = 0; i < 8; i++) {
        float4 o;
        o.x = acc[i][0] + bb.x;
        o.y = acc[i][1] + bb.y;
        o.z = acc[i][2] + bb.z;
        o.w = acc[i][3] + bb.w;
        *(float4*)(C + (size_t)(bm + ty * 8 + i) * N + bn + tx * 4) = o;
    }
}

// ---------------- fused attention v10 ----------------
// Round-12 structure with ONE change: 1024 threads (32 warps) for latency
// cover in the L1-bound QK phase (profiled: L1=61%, issue=44%, occ=25%).
// QK tile 4q x 1k per thread (chain identical to R12/R13: d-ascending x..w
// per (q,col) accumulator -> bit-identical scores). Select/gather/softmax/AV
// run on warps 0..15 exactly as in round 12.
#define QT  16
#define CKC 256
#define NCH (NK / CKC)   // 8
#define CAP 128

struct AttnSmem4 {
    float  s[QT][NK];              // 131072 B
    float4 Ks4[16][CKC + 1];       // 65792 B (dim-major, +1 pad)
    float4 qs4[QT][16];            // 4096 B
    int    hist[QT][256];          // 16384 B
    float  plist[QT][CAP];         // 8192 B
    unsigned short list[QT][CAP];  // 4096 B
    int    cnt[QT];                // 64 B
};                                  // 229696 B (< 232448 limit)

__device__ __forceinline__ unsigned key_of(float f) {
    unsigned u = __float_as_uint(f);
    return (u & 0x80000000u) ? ~u : (u | 0x80000000u);
}
__device__ __forceinline__ float inv_key(unsigned k) {
    unsigned u = (k & 0x80000000u) ? (k ^ 0x80000000u) : ~k;
    return __uint_as_float(u);
}

__global__ __launch_bounds__(1024) void attn_kernel(
    const float* __restrict__ Qg, const float* __restrict__ Kg,
    const float* __restrict__ Vg,
    float* __restrict__ Og)
{
    extern __shared__ char smraw[];
    AttnSmem4* sm = reinterpret_cast<AttnSmem4*>(smraw);

    int tile = blockIdx.x;           // b*1024 + h*128 + qt
    int qt = tile & 127;
    int h  = (tile >> 7) & 7;
    int b  = tile >> 10;
    int tid = threadIdx.x;

    int base_q = b * NQ + qt * QT;
    int base_k = b * NK;
    int hoff = h * DH;

    // stage q (16 rows x 16 float4)
    if (tid < QT * 16) {
        int r = tid >> 4, d4 = tid & 15;
        sm->qs4[r][d4] = *(const float4*)(Qg + (size_t)(base_q + r) * INNER + hoff + d4 * 4);
    }
    __syncthreads();

    int g  = tid >> 8;        // 0..3 -> q rows {4g .. 4g+3} (warp-uniform)
    int kl = tid & 255;       // one k col per thread in the chunk
    int r0 = 4 * g;

    for (int c = 0; c < NCH; c++) {
        // cooperative K-chunk load: gmem coalesced (16 lanes span one K row),
        // stored dim-major for conflict-free compute reads
        {
            const float* src = Kg + (size_t)(base_k + c * CKC) * INNER + hoff;
            #pragma unroll
            for (int i = 0; i < 4; i++) {
                int e = tid + i * 1024;
                int row = e >> 4, d4 = e & 15;
                sm->Ks4[d4][row] = *(const float4*)(src + (size_t)row * INNER + d4 * 4);
            }
        }
        __syncthreads();

        float a0 = 0.f, a1 = 0.f, a2 = 0.f, a3 = 0.f;
        #pragma unroll
        for (int d4 = 0; d4 < 16; d4++) {
            float4 q0 = sm->qs4[r0 + 0][d4];          // warp-uniform -> broadcast
            float4 q1 = sm->qs4[r0 + 1][d4];
            float4 q2 = sm->qs4[r0 + 2][d4];
            float4 q3 = sm->qs4[r0 + 3][d4];
            float4 ka = sm->Ks4[d4][kl];              // lanes adjacent -> conflict-free
            a0 = fmaf(q0.x, ka.x, a0); a0 = fmaf(q0.y, ka.y, a0);
            a0 = fmaf(q0.z, ka.z, a0); a0 = fmaf(q0.w, ka.w, a0);
            a1 = fmaf(q1.x, ka.x, a1); a1 = fmaf(q1.y, ka.y, a1);
            a1 = fmaf(q1.z, ka.z, a1); a1 = fmaf(q1.w, ka.w, a1);
            a2 = fmaf(q2.x, ka.x, a2); a2 = fmaf(q2.y, ka.y, a2);
            a2 = fmaf(q2.z, ka.z, a2); a2 = fmaf(q2.w, ka.w, a2);
            a3 = fmaf(q3.x, ka.x, a3); a3 = fmaf(q3.y, ka.y, a3);
            a3 = fmaf(q3.z, ka.z, a3); a3 = fmaf(q3.w, ka.w, a3);
        }
        int kc = c * CKC;
        sm->s[r0 + 0][kc + kl] = a0 * 0.125f;
        sm->s[r0 + 1][kc + kl] = a1 * 0.125f;
        sm->s[r0 + 2][kc + kl] = a2 * 0.125f;
        sm->s[r0 + 3][kc + kl] = a3 * 0.125f;
        __syncthreads();
    }

    // ---- phases below run on warps 0..15 (one warp per q row) ----
    const unsigned full = 0xFFFFFFFFu;
    int warp = tid >> 5, lane = tid & 31;
    if (warp >= QT) return;
    int r = warp;

    unsigned prefix = 0, pmask = 0;
    int krem = TOPKK;
    #pragma unroll
    for (int shift = 24; shift >= 0; shift -= 8) {
        for (int bi = lane; bi < 256; bi += 32) sm->hist[r][bi] = 0;
        __syncwarp();
        // vectorized scan: lane owns 4 consecutive elems per iter (LDS.128)
        #pragma unroll 4
        for (int i = 0; i < 16; i++) {
            int j = lane * 4 + i * 128;
            float4 sv = *(const float4*)&sm->s[r][j];
            unsigned u0 = key_of(sv.x), u1 = key_of(sv.y);
            unsigned u2 = key_of(sv.z), u3 = key_of(sv.w);
            bool p0 = ((u0 & pmask) == prefix);
            bool p1 = ((u1 & pmask) == prefix);
            bool p2 = ((u2 & pmask) == prefix);
            bool p3 = ((u3 & pmask) == prefix);
            if (p0 | p1 | p2 | p3) {
                int b0 = (u0 >> shift) & 255;
                int b1 = (u1 >> shift) & 255;
                int b2 = (u2 >> shift) & 255;
                int b3 = (u3 >> shift) & 255;
                if (p0 & p1 & p2 & p3 & (b0 == b1) & (b0 == b2) & (b0 == b3)) {
                    atomicAdd(&sm->hist[r][b0], 4);
                } else {
                    if (p0) atomicAdd(&sm->hist[r][b0], 1);
                    if (p1) atomicAdd(&sm->hist[r][b1], 1);
                    if (p2) atomicAdd(&sm->hist[r][b2], 1);
                    if (p3) atomicAdd(&sm->hist[r][b3], 1);
                }
            }
        }
        __syncwarp();
        int basebin = 255 - 8 * lane;
        int gsum = 0;
        #pragma unroll
        for (int i = 0; i < 8; i++) gsum += sm->hist[r][basebin - i];
        int inc = gsum;
        #pragma unroll
        for (int off = 1; off < 32; off <<= 1) {
            int v = __shfl_up_sync(full, inc, off);
            if (lane >= off) inc += v;
        }
        int excl = inc - gsum;
        unsigned bal = __ballot_sync(full, (excl < krem) && (krem <= inc));
        int selLane = __ffs(bal) - 1;
        int exclSel = __shfl_sync(full, excl, selLane);
        int need = krem - exclSel;
        int gb = 255 - 8 * selLane;
        int selBin = -1, cc = 0, newNeed = 0;
        for (int i = 0; i < 8; i++) {
            int hh = sm->hist[r][gb - i];
            if (selBin < 0 && need <= cc + hh) { selBin = gb - i; newNeed = need - cc; }
            cc += hh;
        }
        krem = newNeed;
        prefix |= ((unsigned)selBin) << shift;
        pmask  |= (0xFFu << shift);
        __syncwarp();
    }
    float vkf = inv_key(prefix);

    // ---- vectorized deterministic gather of kept indices + row max ----
    int cbase = 0;
    float m = -FLT_MAX;
    unsigned ltm = (1u << lane) - 1u;
    #pragma unroll 4
    for (int i = 0; i < 16; i++) {
        int j = lane * 4 + i * 128;
        float4 sv = *(const float4*)&sm->s[r][j];
        bool k0 = (sv.x >= vkf), k1 = (sv.y >= vkf);
        bool k2 = (sv.z >= vkf), k3 = (sv.w >= vkf);
        unsigned b0 = __ballot_sync(full, k0);
        unsigned b1 = __ballot_sync(full, k1);
        unsigned b2 = __ballot_sync(full, k2);
        unsigned b3 = __ballot_sync(full, k3);
        m = fmaxf(m, fmaxf(fmaxf(sv.x, sv.y), fmaxf(sv.z, sv.w)));
        if (k0 | k1 | k2 | k3) {
            int pos = cbase + __popc(b0 & ltm) + __popc(b1 & ltm)
                            + __popc(b2 & ltm) + __popc(b3 & ltm);
            if (k0) { if (pos < CAP) sm->list[r][pos] = (unsigned short)j;       pos++; }
            if (k1) { if (pos < CAP) sm->list[r][pos] = (unsigned short)(j + 1); pos++; }
            if (k2) { if (pos < CAP) sm->list[r][pos] = (unsigned short)(j + 2); pos++; }
            if (k3) { if (pos < CAP) sm->list[r][pos] = (unsigned short)(j + 3); pos++; }
        }
        cbase += __popc(b0) + __popc(b1) + __popc(b2) + __popc(b3);
    }
    #pragma unroll
    for (int off = 16; off; off >>= 1) m = fmaxf(m, __shfl_xor_sync(full, m, off));
    if (lane == 0) sm->cnt[r] = cbase;
    __syncwarp();
    int n = sm->cnt[r];

    float acc0 = 0.f, acc1 = 0.f, sum = 0.f;
    const float* Vb = Vg + (size_t)base_k * INNER + hoff;

    if (n <= CAP) {
        float ls = 0.f;
        for (int e = lane; e < n; e += 32) {
            int j = sm->list[r][e];
            float p = expf(sm->s[r][j] - m);
            sm->plist[r][e] = p;
            ls += p;
        }
        #pragma unroll
        for (int off = 16; off; off >>= 1) ls += __shfl_xor_sync(full, ls, off);
        sum = ls;
        __syncwarp();
        #pragma unroll 4
        for (int e = 0; e < n; e++) {
            float p = sm->plist[r][e];
            int j = sm->list[r][e];
            const float* vp = Vb + (size_t)j * INNER;
            acc0 = fmaf(p, vp[lane],      acc0);
            acc1 = fmaf(p, vp[lane + 32], acc1);
        }
    } else {
        float ls = 0.f;
        for (int j = 0; j < NK; j++) {
            float sv = sm->s[r][j];
            if (sv >= vkf) {
                float p = expf(sv - m);
                ls += p;
                const float* vp = Vb + (size_t)j * INNER;
                acc0 = fmaf(p, vp[lane],      acc0);
                acc1 = fmaf(p, vp[lane + 32], acc1);
            }
        }
        sum = ls;
    }

    float invs = 1.0f / sum;
    float* op = Og + (size_t)(base_q + r) * INNER + hoff;
    op[lane]      = acc0 * invs;
    op[lane + 32] = acc1 * invs;
}

// ---------------- launch ----------------
extern "C" void kernel_launch(void* const* d_in, const int* in_sizes, int n_in,
                              void* d_out, int out_size)
{
    const float* x       = (const float*)d_in[0];
    const float* context = (const float*)d_in[1];
    // d_in[2]/d_in[3] are the bool masks; constant all-True in this problem.
    const float* Wq = (const float*)d_in[4];
    const float* bq = (const float*)d_in[5];
    const float* Wk = (const float*)d_in[6];
    const float* bk = (const float*)d_in[7];
    const float* Wv = (const float*)d_in[8];
    const float* bv = (const float*)d_in[9];
    const float* Wo = (const float*)d_in[10];
    const float* bo = (const float*)d_in[11];
    float* out = (float*)d_out;

    void *pAq, *pAk, *pQ, *pK, *pV, *pO;
    cudaGetSymbolAddress(&pAq, g_Aq);
    cudaGetSymbolAddress(&pAk, g_Ak);
    cudaGetSymbolAddress(&pQ,  g_Q);
    cudaGetSymbolAddress(&pK,  g_K);
    cudaGetSymbolAddress(&pV,  g_V);
    cudaGetSymbolAddress(&pO,  g_O);
    float* Aq = (float*)pAq; float* Ak = (float*)pAk;
    float* Qd = (float*)pQ;  float* Kd = (float*)pK;
    float* Vd = (float*)pV;  float* Od = (float*)pO;

    cudaFuncSetAttribute(attn_kernel, cudaFuncAttributeMaxDynamicSharedMemorySize,
                         (int)sizeof(AttnSmem4));

    enc_kernel<<<(NQ + 255) / 256, 256>>>();

    int tot = MROWS * DWP;
    concat_kernel<<<(tot + 255) / 256, 256>>>(x, context);

    dim3 gg(INNER / 64, MROWS / 128);   // (8, 32)
    gemm_bias<<<gg, 256>>>(Aq, DWP, Wq, bq, Qd, MROWS, INNER, DWP);
    gemm_bias<<<gg, 256>>>(Ak, DWP, Wk, bk, Kd, MROWS, INNER, DWP);
    gemm_bias<<<gg, 256>>>(context, DIMM, Wv, bv, Vd, MROWS, INNER, DIMM);

    attn_kernel<<<BB * HH * (NQ / QT), 1024, sizeof(AttnSmem4)>>>(Qd, Kd, Vd, Od);

    gemm_bias<<<gg, 256>>>(Od, INNER, Wo, bo, out, MROWS, DIMM, INNER);
}

// round 16
// speedup vs baseline: 1.0140x; 1.0140x over previous
#include <cuda_runtime.h>
#include <math.h>
#include <cfloat>
#include <stdint.h>

// ---------------- problem constants ----------------
#define BB     2
#define NQ     2048
#define NK     2048
#define DIMM   512
#define HH     8
#define DH     64
#define INNER  512
#define NBANDS 32
#define DWP    577      // DIM + 2*NUM_BANDS + 1
#define TOPKK  64
#define MROWS  (BB*NQ)  // 4096

// ---------------- scratch (device globals; no cudaMalloc allowed) ----------------
__device__ float g_enc[NQ * 65];
__device__ float g_Q [(size_t)MROWS * INNER];
__device__ float g_K [(size_t)MROWS * INNER];
__device__ float g_V [(size_t)MROWS * INNER];
__device__ float g_O [(size_t)MROWS * INNER];

// ---------------- f32x2 packed helpers (sm_103a) ----------------
__device__ __forceinline__ unsigned long long pk2(float lo, float hi) {
    unsigned long long r;
    asm("mov.b64 %0, {%1, %2};" : "=l"(r) : "f"(lo), "f"(hi));
    return r;
}
__device__ __forceinline__ void upk2(unsigned long long v, float& lo, float& hi) {
    asm("mov.b64 {%0, %1}, %2;" : "=f"(lo), "=f"(hi) : "l"(v));
}
__device__ __forceinline__ unsigned long long fma2(unsigned long long a,
                                                   unsigned long long b,
                                                   unsigned long long c) {
    unsigned long long d;
    asm("fma.rn.f32x2 %0, %1, %2, %3;" : "=l"(d) : "l"(a), "l"(b), "l"(c));
    return d;
}

// ---------------- fourier encode ----------------
__global__ void enc_kernel() {
    int i = blockIdx.x * blockDim.x + threadIdx.x;
    if (i >= NQ) return;
    float step = 2.0f / 2047.0f;
    float pos = fmaf((float)i, step, -1.0f);
    g_enc[i * 65 + 64] = pos;
    #pragma unroll 4
    for (int b = 0; b < NBANDS; b++) {
        float sc = 1.0f + 29.0f * (float)b / 31.0f;   // linspace(1, 30, 32)
        float xs = (pos * sc) * 3.14159265358979323846f;
        g_enc[i * 65 + b]          = sinf(xs);
        g_enc[i * 65 + NBANDS + b] = cosf(xs);
    }
}

// ---------------- f32x2 GEMM core (round-10 chains, verbatim math) ----------------
// CAT=0: plain A[m][k] with leading dim lda.
// CAT=1: virtual A = [X (512 cols) | g_enc (65 cols)], row m -> enc row (m & 2047).
template <int CAT>
__device__ __forceinline__ void gemm_core(
    const float* __restrict__ A, int lda,
    const float* __restrict__ W,
    const float* __restrict__ bias,
    float* __restrict__ C,
    int N, int K)
{
    __shared__ float As[16][132];
    __shared__ float Bs[16][64];

    int bm = blockIdx.y * 128;
    int bn = blockIdx.x * 64;
    int tid = threadIdx.x;
    int tx = tid & 15;
    int ty = tid >> 4;

    unsigned long long accP[4][2], accQ[4][2];
    #pragma unroll
    for (int ip = 0; ip < 4; ip++)
        #pragma unroll
        for (int jp = 0; jp < 2; jp++) { accP[ip][jp] = 0ull; accQ[ip][jp] = 0ull; }

    for (int k0 = 0; k0 < K; k0 += 16) {
        #pragma unroll
        for (int i = 0; i < 8; i++) {
            int e = tid + i * 256;
            int m = e >> 4, kk = e & 15;
            int gk = k0 + kk;
            float v = 0.0f;
            if (gk < K) {
                if (CAT) {
                    int row = bm + m;
                    v = (gk < DIMM) ? A[(size_t)row * DIMM + gk]
                                    : g_enc[(row & (NQ - 1)) * 65 + (gk - DIMM)];
                } else {
                    v = A[(size_t)(bm + m) * lda + gk];
                }
            }
            As[kk][m] = v;
        }
        {
            int kk = tid >> 4;
            int nc = (tid & 15) << 2;
            int gk = k0 + kk;
            float4 v = make_float4(0.f, 0.f, 0.f, 0.f);
            if (gk < K) v = *(const float4*)(W + (size_t)gk * N + bn + nc);
            *(float4*)&Bs[kk][nc] = v;
        }
        __syncthreads();
        #pragma unroll
        for (int kk = 0; kk < 16; kk++) {
            float4 a0 = *(const float4*)&As[kk][ty * 8];
            float4 a1 = *(const float4*)&As[kk][ty * 8 + 4];
            float4 bv = *(const float4*)&Bs[kk][tx * 4];
            unsigned long long ap[4];
            ap[0] = pk2(a0.x, a0.y);
            ap[1] = pk2(a0.z, a0.w);
            ap[2] = pk2(a1.x, a1.y);
            ap[3] = pk2(a1.z, a1.w);
            unsigned long long bP0 = pk2(bv.x, bv.y);
            unsigned long long bP1 = pk2(bv.z, bv.w);
            unsigned long long bQ0 = pk2(bv.y, bv.x);
            unsigned long long bQ1 = pk2(bv.w, bv.z);
            #pragma unroll
            for (int ip = 0; ip < 4; ip++) {
                accP[ip][0] = fma2(ap[ip], bP0, accP[ip][0]);
                accQ[ip][0] = fma2(ap[ip], bQ0, accQ[ip][0]);
                accP[ip][1] = fma2(ap[ip], bP1, accP[ip][1]);
                accQ[ip][1] = fma2(ap[ip], bQ1, accQ[ip][1]);
            }
        }
        __syncthreads();
    }

    float acc[8][4];
    #pragma unroll
    for (int ip = 0; ip < 4; ip++) {
        #pragma unroll
        for (int jp = 0; jp < 2; jp++) {
            float plo, phi, qlo, qhi;
            upk2(accP[ip][jp], plo, phi);
            upk2(accQ[ip][jp], qlo, qhi);
            acc[2 * ip][2 * jp]         = plo;
            acc[2 * ip + 1][2 * jp + 1] = phi;
            acc[2 * ip][2 * jp + 1]     = qlo;
            acc[2 * ip + 1][2 * jp]     = qhi;
        }
    }

    float4 bb = *(const float4*)(bias + bn + tx * 4);
    #pragma unroll
    for (int i = 0; i < 8; i++) {
        float4 o;
        o.x = acc[i][0] + bb.x;
        o.y = acc[i][1] + bb.y;
        o.z = acc[i][2] + bb.z;
        o.w = acc[i][3] + bb.w;
        *(float4*)(C + (size_t)(bm + ty * 8 + i) * N + bn + tx * 4) = o;
    }
}

__global__ __launch_bounds__(256) void gemm_bias(
    const float* __restrict__ A, int lda,
    const float* __restrict__ W,
    const float* __restrict__ bias,
    float* __restrict__ C,
    int M, int N, int K)
{
    gemm_core<0>(A, lda, W, bias, C, N, K);
}

// Q/K projection: A = [X | enc] generated on the fly (concat fused away)
__global__ __launch_bounds__(256) void gemm_bias_cat(
    const float* __restrict__ X,
    const float* __restrict__ W,
    const float* __restrict__ bias,
    float* __restrict__ C)
{
    gemm_core<1>(X, DIMM, W, bias, C, INNER, DWP);
}

// ---------------- fused attention (round-12 winner, verbatim) ----------------
#define QT  16
#define CKC 256
#define NCH (NK / CKC)   // 8
#define CAP 128

struct AttnSmem4 {
    float  s[QT][NK];              // 131072 B
    float4 Ks4[16][CKC + 1];       // 65792 B (dim-major, +1 pad)
    float4 qs4[QT][16];            // 4096 B
    int    hist[QT][256];          // 16384 B
    float  plist[QT][CAP];         // 8192 B
    unsigned short list[QT][CAP];  // 4096 B
    int    cnt[QT];                // 64 B
};                                  // 229696 B (< 232448 limit)

__device__ __forceinline__ unsigned key_of(float f) {
    unsigned u = __float_as_uint(f);
    return (u & 0x80000000u) ? ~u : (u | 0x80000000u);
}
__device__ __forceinline__ float inv_key(unsigned k) {
    unsigned u = (k & 0x80000000u) ? (k ^ 0x80000000u) : ~k;
    return __uint_as_float(u);
}

__global__ __launch_bounds__(512) void attn_kernel(
    const float* __restrict__ Qg, const float* __restrict__ Kg,
    const float* __restrict__ Vg,
    float* __restrict__ Og)
{
    extern __shared__ char smraw[];
    AttnSmem4* sm = reinterpret_cast<AttnSmem4*>(smraw);

    int tile = blockIdx.x;           // b*1024 + h*128 + qt
    int qt = tile & 127;
    int h  = (tile >> 7) & 7;
    int b  = tile >> 10;
    int tid = threadIdx.x;

    int base_q = b * NQ + qt * QT;
    int base_k = b * NK;
    int hoff = h * DH;

    // stage q (16 rows x 16 float4)
    if (tid < QT * 16) {
        int r = tid >> 4, d4 = tid & 15;
        sm->qs4[r][d4] = *(const float4*)(Qg + (size_t)(base_q + r) * INNER + hoff + d4 * 4);
    }
    __syncthreads();

    int g  = tid >> 7;        // 0..3 -> q rows {4g .. 4g+3} (warp-uniform)
    int kl = tid & 127;       // k cols {kl, kl+128} in chunk
    int r0 = 4 * g;

    for (int c = 0; c < NCH; c++) {
        // cooperative K-chunk load: gmem coalesced (16 lanes span one K row),
        // stored dim-major for conflict-free compute reads
        {
            const float* src = Kg + (size_t)(base_k + c * CKC) * INNER + hoff;
            #pragma unroll
            for (int i = 0; i < 8; i++) {
                int e = tid + i * 512;
                int row = e >> 4, d4 = e & 15;
                sm->Ks4[d4][row] = *(const float4*)(src + (size_t)row * INNER + d4 * 4);
            }
        }
        __syncthreads();

        float a0[2] = {0.f, 0.f};
        float a1[2] = {0.f, 0.f};
        float a2[2] = {0.f, 0.f};
        float a3[2] = {0.f, 0.f};
        #pragma unroll
        for (int d4 = 0; d4 < 16; d4++) {
            float4 q0 = sm->qs4[r0 + 0][d4];          // warp-uniform -> broadcast
            float4 q1 = sm->qs4[r0 + 1][d4];
            float4 q2 = sm->qs4[r0 + 2][d4];
            float4 q3 = sm->qs4[r0 + 3][d4];
            float4 ka = sm->Ks4[d4][kl];              // lanes adjacent -> conflict-free
            float4 kb = sm->Ks4[d4][kl + 128];
            a0[0] = fmaf(q0.x, ka.x, a0[0]); a0[0] = fmaf(q0.y, ka.y, a0[0]);
            a0[0] = fmaf(q0.z, ka.z, a0[0]); a0[0] = fmaf(q0.w, ka.w, a0[0]);
            a0[1] = fmaf(q0.x, kb.x, a0[1]); a0[1] = fmaf(q0.y, kb.y, a0[1]);
            a0[1] = fmaf(q0.z, kb.z, a0[1]); a0[1] = fmaf(q0.w, kb.w, a0[1]);
            a1[0] = fmaf(q1.x, ka.x, a1[0]); a1[0] = fmaf(q1.y, ka.y, a1[0]);
            a1[0] = fmaf(q1.z, ka.z, a1[0]); a1[0] = fmaf(q1.w, ka.w, a1[0]);
            a1[1] = fmaf(q1.x, kb.x, a1[1]); a1[1] = fmaf(q1.y, kb.y, a1[1]);
            a1[1] = fmaf(q1.z, kb.z, a1[1]); a1[1] = fmaf(q1.w, kb.w, a1[1]);
            a2[0] = fmaf(q2.x, ka.x, a2[0]); a2[0] = fmaf(q2.y, ka.y, a2[0]);
            a2[0] = fmaf(q2.z, ka.z, a2[0]); a2[0] = fmaf(q2.w, ka.w, a2[0]);
            a2[1] = fmaf(q2.x, kb.x, a2[1]); a2[1] = fmaf(q2.y, kb.y, a2[1]);
            a2[1] = fmaf(q2.z, kb.z, a2[1]); a2[1] = fmaf(q2.w, kb.w, a2[1]);
            a3[0] = fmaf(q3.x, ka.x, a3[0]); a3[0] = fmaf(q3.y, ka.y, a3[0]);
            a3[0] = fmaf(q3.z, ka.z, a3[0]); a3[0] = fmaf(q3.w, ka.w, a3[0]);
            a3[1] = fmaf(q3.x, kb.x, a3[1]); a3[1] = fmaf(q3.y, kb.y, a3[1]);
            a3[1] = fmaf(q3.z, kb.z, a3[1]); a3[1] = fmaf(q3.w, kb.w, a3[1]);
        }
        int kc = c * CKC;
        sm->s[r0 + 0][kc + kl]       = a0[0] * 0.125f;
        sm->s[r0 + 0][kc + kl + 128] = a0[1] * 0.125f;
        sm->s[r0 + 1][kc + kl]       = a1[0] * 0.125f;
        sm->s[r0 + 1][kc + kl + 128] = a1[1] * 0.125f;
        sm->s[r0 + 2][kc + kl]       = a2[0] * 0.125f;
        sm->s[r0 + 2][kc + kl + 128] = a2[1] * 0.125f;
        sm->s[r0 + 3][kc + kl]       = a3[0] * 0.125f;
        sm->s[r0 + 3][kc + kl + 128] = a3[1] * 0.125f;
        __syncthreads();
    }

    // ---- per-warp exact radix select of the 64th-largest value ----
    const unsigned full = 0xFFFFFFFFu;
    int warp = tid >> 5, lane = tid & 31;
    int r = warp;                       // 16 warps == QT rows

    unsigned prefix = 0, pmask = 0;
    int krem = TOPKK;
    #pragma unroll
    for (int shift = 24; shift >= 0; shift -= 8) {
        for (int bi = lane; bi < 256; bi += 32) sm->hist[r][bi] = 0;
        __syncwarp();
        // vectorized scan: lane owns 4 consecutive elems per iter (LDS.128)
        #pragma unroll 4
        for (int i = 0; i < 16; i++) {
            int j = lane * 4 + i * 128;
            float4 sv = *(const float4*)&sm->s[r][j];
            unsigned u0 = key_of(sv.x), u1 = key_of(sv.y);
            unsigned u2 = key_of(sv.z), u3 = key_of(sv.w);
            bool p0 = ((u0 & pmask) == prefix);
            bool p1 = ((u1 & pmask) == prefix);
            bool p2 = ((u2 & pmask) == prefix);
            bool p3 = ((u3 & pmask) == prefix);
            if (p0 | p1 | p2 | p3) {
                int b0 = (u0 >> shift) & 255;
                int b1 = (u1 >> shift) & 255;
                int b2 = (u2 >> shift) & 255;
                int b3 = (u3 >> shift) & 255;
                if (p0 & p1 & p2 & p3 & (b0 == b1) & (b0 == b2) & (b0 == b3)) {
                    atomicAdd(&sm->hist[r][b0], 4);
                } else {
                    if (p0) atomicAdd(&sm->hist[r][b0], 1);
                    if (p1) atomicAdd(&sm->hist[r][b1], 1);
                    if (p2) atomicAdd(&sm->hist[r][b2], 1);
                    if (p3) atomicAdd(&sm->hist[r][b3], 1);
                }
            }
        }
        __syncwarp();
        int basebin = 255 - 8 * lane;
        int gsum = 0;
        #pragma unroll
        for (int i = 0; i < 8; i++) gsum += sm->hist[r][basebin - i];
        int inc = gsum;
        #pragma unroll
        for (int off = 1; off < 32; off <<= 1) {
            int v = __shfl_up_sync(full, inc, off);
            if (lane >= off) inc += v;
        }
        int excl = inc - gsum;
        unsigned bal = __ballot_sync(full, (excl < krem) && (krem <= inc));
        int selLane = __ffs(bal) - 1;
        int exclSel = __shfl_sync(full, excl, selLane);
        int need = krem - exclSel;
        int gb = 255 - 8 * selLane;
        int selBin = -1, cc = 0, newNeed = 0;
        for (int i = 0; i < 8; i++) {
            int hh = sm->hist[r][gb - i];
            if (selBin < 0 && need <= cc + hh) { selBin = gb - i; newNeed = need - cc; }
            cc += hh;
        }
        krem = newNeed;
        prefix |= ((unsigned)selBin) << shift;
        pmask  |= (0xFFu << shift);
        __syncwarp();
    }
    float vkf = inv_key(prefix);

    // ---- vectorized deterministic gather of kept indices + row max ----
    int cbase = 0;
    float m = -FLT_MAX;
    unsigned ltm = (1u << lane) - 1u;
    #pragma unroll 4
    for (int i = 0; i < 16; i++) {
        int j = lane * 4 + i * 128;
        float4 sv = *(const float4*)&sm->s[r][j];
        bool k0 = (sv.x >= vkf), k1 = (sv.y >= vkf);
        bool k2 = (sv.z >= vkf), k3 = (sv.w >= vkf);
        unsigned b0 = __ballot_sync(full, k0);
        unsigned b1 = __ballot_sync(full, k1);
        unsigned b2 = __ballot_sync(full, k2);
        unsigned b3 = __ballot_sync(full, k3);
        m = fmaxf(m, fmaxf(fmaxf(sv.x, sv.y), fmaxf(sv.z, sv.w)));
        if (k0 | k1 | k2 | k3) {
            int pos = cbase + __popc(b0 & ltm) + __popc(b1 & ltm)
                            + __popc(b2 & ltm) + __popc(b3 & ltm);
            if (k0) { if (pos < CAP) sm->list[r][pos] = (unsigned short)j;       pos++; }
            if (k1) { if (pos < CAP) sm->list[r][pos] = (unsigned short)(j + 1); pos++; }
            if (k2) { if (pos < CAP) sm->list[r][pos] = (unsigned short)(j + 2); pos++; }
            if (k3) { if (pos < CAP) sm->list[r][pos] = (unsigned short)(j + 3); pos++; }
        }
        cbase += __popc(b0) + __popc(b1) + __popc(b2) + __popc(b3);
    }
    #pragma unroll
    for (int off = 16; off; off >>= 1) m = fmaxf(m, __shfl_xor_sync(full, m, off));
    if (lane == 0) sm->cnt[r] = cbase;
    __syncwarp();
    int n = sm->cnt[r];

    float acc0 = 0.f, acc1 = 0.f, sum = 0.f;
    const float* Vb = Vg + (size_t)base_k * INNER + hoff;

    if (n <= CAP) {
        float ls = 0.f;
        for (int e = lane; e < n; e += 32) {
            int j = sm->list[r][e];
            float p = expf(sm->s[r][j] - m);
            sm->plist[r][e] = p;
            ls += p;
        }
        #pragma unroll
        for (int off = 16; off; off >>= 1) ls += __shfl_xor_sync(full, ls, off);
        sum = ls;
        __syncwarp();
        #pragma unroll 4
        for (int e = 0; e < n; e++) {
            float p = sm->plist[r][e];
            int j = sm->list[r][e];
            const float* vp = Vb + (size_t)j * INNER;
            acc0 = fmaf(p, vp[lane],      acc0);
            acc1 = fmaf(p, vp[lane + 32], acc1);
        }
    } else {
        float ls = 0.f;
        for (int j = 0; j < NK; j++) {
            float sv = sm->s[r][j];
            if (sv >= vkf) {
                float p = expf(sv - m);
                ls += p;
                const float* vp = Vb + (size_t)j * INNER;
                acc0 = fmaf(p, vp[lane],      acc0);
                acc1 = fmaf(p, vp[lane + 32], acc1);
            }
        }
        sum = ls;
    }

    float invs = 1.0f / sum;
    float* op = Og + (size_t)(base_q + r) * INNER + hoff;
    op[lane]      = acc0 * invs;
    op[lane + 32] = acc1 * invs;
}

// ---------------- launch ----------------
extern "C" void kernel_launch(void* const* d_in, const int* in_sizes, int n_in,
                              void* d_out, int out_size)
{
    const float* x       = (const float*)d_in[0];
    const float* context = (const float*)d_in[1];
    // d_in[2]/d_in[3] are the bool masks; constant all-True in this problem.
    const float* Wq = (const float*)d_in[4];
    const float* bq = (const float*)d_in[5];
    const float* Wk = (const float*)d_in[6];
    const float* bk = (const float*)d_in[7];
    const float* Wv = (const float*)d_in[8];
    const float* bv = (const float*)d_in[9];
    const float* Wo = (const float*)d_in[10];
    const float* bo = (const float*)d_in[11];
    float* out = (float*)d_out;

    void *pQ, *pK, *pV, *pO;
    cudaGetSymbolAddress(&pQ,  g_Q);
    cudaGetSymbolAddress(&pK,  g_K);
    cudaGetSymbolAddress(&pV,  g_V);
    cudaGetSymbolAddress(&pO,  g_O);
    float* Qd = (float*)pQ;  float* Kd = (float*)pK;
    float* Vd = (float*)pV;  float* Od = (float*)pO;

    cudaFuncSetAttribute(attn_kernel, cudaFuncAttributeMaxDynamicSharedMemorySize,
                         (int)sizeof(AttnSmem4));

    enc_kernel<<<(NQ + 255) / 256, 256>>>();

    dim3 gg(INNER / 64, MROWS / 128);   // (8, 32)
    // Q/K projections with concat fused into the A-tile loader
    gemm_bias_cat<<<gg, 256>>>(x,       Wq, bq, Qd);
    gemm_bias_cat<<<gg, 256>>>(context, Wk, bk, Kd);
    gemm_bias<<<gg, 256>>>(context, DIMM, Wv, bv, Vd, MROWS, INNER, DIMM);

    attn_kernel<<<BB * HH * (NQ / QT), 512, sizeof(AttnSmem4)>>>(Qd, Kd, Vd, Od);

    gemm_bias<<<gg, 256>>>(Od, INNER, Wo, bo, out, MROWS, DIMM, INNER);
}

// round 17
// speedup vs baseline: 1.1397x; 1.1240x over previous
#include <cuda_runtime.h>
#include <math.h>
#include <cfloat>
#include <stdint.h>

// ---------------- problem constants ----------------
#define BB     2
#define NQ     2048
#define NK     2048
#define DIMM   512
#define HH     8
#define DH     64
#define INNER  512
#define NBANDS 32
#define DWP    577      // DIM + 2*NUM_BANDS + 1
#define TOPKK  64
#define MROWS  (BB*NQ)  // 4096

typedef unsigned long long ull;

// ---------------- scratch (device globals; no cudaMalloc allowed) ----------------
__device__ float g_enc[NQ * 65];
__device__ float g_Aq[(size_t)MROWS * DWP];
__device__ float g_Ak[(size_t)MROWS * DWP];
__device__ float g_Q [(size_t)MROWS * INNER];
__device__ float g_K [(size_t)MROWS * INNER];
__device__ float g_V [(size_t)MROWS * INNER];
__device__ float g_O [(size_t)MROWS * INNER];

// ---------------- f32x2 packed helpers (sm_103a) ----------------
__device__ __forceinline__ ull pk2(float lo, float hi) {
    ull r;
    asm("mov.b64 %0, {%1, %2};" : "=l"(r) : "f"(lo), "f"(hi));
    return r;
}
__device__ __forceinline__ void upk2(ull v, float& lo, float& hi) {
    asm("mov.b64 {%0, %1}, %2;" : "=f"(lo), "=f"(hi) : "l"(v));
}
__device__ __forceinline__ ull fma2(ull a, ull b, ull c) {
    ull d;
    asm("fma.rn.f32x2 %0, %1, %2, %3;" : "=l"(d) : "l"(a), "l"(b), "l"(c));
    return d;
}

// ---------------- fourier encode ----------------
__global__ void enc_kernel() {
    int i = blockIdx.x * blockDim.x + threadIdx.x;
    if (i >= NQ) return;
    float step = 2.0f / 2047.0f;
    float pos = fmaf((float)i, step, -1.0f);
    g_enc[i * 65 + 64] = pos;
    #pragma unroll 4
    for (int b = 0; b < NBANDS; b++) {
        float sc = 1.0f + 29.0f * (float)b / 31.0f;   // linspace(1, 30, 32)
        float xs = (pos * sc) * 3.14159265358979323846f;
        g_enc[i * 65 + b]          = sinf(xs);
        g_enc[i * 65 + NBANDS + b] = cosf(xs);
    }
}

// ---------------- concat [x | enc] and [context | enc] ----------------
__global__ void concat_kernel(const float* __restrict__ x, const float* __restrict__ ctx) {
    int idx = blockIdx.x * blockDim.x + threadIdx.x;
    const int total = MROWS * DWP;
    if (idx >= total) return;
    int row = idx / DWP;
    int c   = idx - row * DWP;
    if (c < DIMM) {
        g_Aq[idx] = x  [(size_t)row * DIMM + c];
        g_Ak[idx] = ctx[(size_t)row * DIMM + c];
    } else {
        int i = row & (NQ - 1);
        float e = g_enc[i * 65 + (c - DIMM)];
        g_Aq[idx] = e;
        g_Ak[idx] = e;
    }
}

// ---------------- fp32 tiled GEMM with packed f32x2 FMA (round-10, verbatim) ----------------
__global__ __launch_bounds__(256) void gemm_bias(
    const float* __restrict__ A, int lda,
    const float* __restrict__ W,
    const float* __restrict__ bias,
    float* __restrict__ C,
    int M, int N, int K)
{
    __shared__ float As[16][132];
    __shared__ float Bs[16][64];

    int bm = blockIdx.y * 128;
    int bn = blockIdx.x * 64;
    int tid = threadIdx.x;
    int tx = tid & 15;
    int ty = tid >> 4;

    ull accP[4][2], accQ[4][2];
    #pragma unroll
    for (int ip = 0; ip < 4; ip++)
        #pragma unroll
        for (int jp = 0; jp < 2; jp++) { accP[ip][jp] = 0ull; accQ[ip][jp] = 0ull; }

    for (int k0 = 0; k0 < K; k0 += 16) {
        #pragma unroll
        for (int i = 0; i < 8; i++) {
            int e = tid + i * 256;
            int m = e >> 4, kk = e & 15;
            int gk = k0 + kk;
            As[kk][m] = (gk < K) ? A[(size_t)(bm + m) * lda + gk] : 0.0f;
        }
        {
            int kk = tid >> 4;
            int nc = (tid & 15) << 2;
            int gk = k0 + kk;
            float4 v = make_float4(0.f, 0.f, 0.f, 0.f);
            if (gk < K) v = *(const float4*)(W + (size_t)gk * N + bn + nc);
            *(float4*)&Bs[kk][nc] = v;
        }
        __syncthreads();
        #pragma unroll
        for (int kk = 0; kk < 16; kk++) {
            float4 a0 = *(const float4*)&As[kk][ty * 8];
            float4 a1 = *(const float4*)&As[kk][ty * 8 + 4];
            float4 bv = *(const float4*)&Bs[kk][tx * 4];
            ull ap[4];
            ap[0] = pk2(a0.x, a0.y);
            ap[1] = pk2(a0.z, a0.w);
            ap[2] = pk2(a1.x, a1.y);
            ap[3] = pk2(a1.z, a1.w);
            ull bP0 = pk2(bv.x, bv.y);
            ull bP1 = pk2(bv.z, bv.w);
            ull bQ0 = pk2(bv.y, bv.x);
            ull bQ1 = pk2(bv.w, bv.z);
            #pragma unroll
            for (int ip = 0; ip < 4; ip++) {
                accP[ip][0] = fma2(ap[ip], bP0, accP[ip][0]);
                accQ[ip][0] = fma2(ap[ip], bQ0, accQ[ip][0]);
                accP[ip][1] = fma2(ap[ip], bP1, accP[ip][1]);
                accQ[ip][1] = fma2(ap[ip], bQ1, accQ[ip][1]);
            }
        }
        __syncthreads();
    }

    float acc[8][4];
    #pragma unroll
    for (int ip = 0; ip < 4; ip++) {
        #pragma unroll
        for (int jp = 0; jp < 2; jp++) {
            float plo, phi, qlo, qhi;
            upk2(accP[ip][jp], plo, phi);
            upk2(accQ[ip][jp], qlo, qhi);
            acc[2 * ip][2 * jp]         = plo;
            acc[2 * ip + 1][2 * jp + 1] = phi;
            acc[2 * ip][2 * jp + 1]     = qlo;
            acc[2 * ip + 1][2 * jp]     = qhi;
        }
    }

    float4 bb = *(const float4*)(bias + bn + tx * 4);
    #pragma unroll
    for (int i = 0; i < 8; i++) {
        float4 o;
        o.x = acc[i][0] + bb.x;
        o.y = acc[i][1] + bb.y;
        o.z = acc[i][2] + bb.z;
        o.w = acc[i][3] + bb.w;
        *(float4*)(C + (size_t)(bm + ty * 8 + i) * N + bn + tx * 4) = o;
    }
}

// ---------------- fused attention v11 ----------------
// Round-12 winner with ONE change: QK inner product uses fma.rn.f32x2 with
// row-pair packing (lane-lo = even row's chain, lane-hi = odd row's chain,
// identical operand order per chain -> bit-identical scores). q is staged
// pre-paired in smem; K duplicates via mov.b64 {r,r} on the ALU pipe.
#define QT  16
#define CKC 256
#define NCH (NK / CKC)   // 8
#define CAP 128

struct AttnSmem4 {
    float  s[QT][NK];              // 131072 B
    float4 Ks4[16][CKC + 1];       // 65792 B (dim-major, +1 pad)
    ull    qp[8][64];              // 4096 B  (paired q rows, f32x2)
    int    hist[QT][256];          // 16384 B
    float  plist[QT][CAP];         // 8192 B
    unsigned short list[QT][CAP];  // 4096 B
    int    cnt[QT];                // 64 B
};                                  // 229696 B (< 232448 limit)

__device__ __forceinline__ unsigned key_of(float f) {
    unsigned u = __float_as_uint(f);
    return (u & 0x80000000u) ? ~u : (u | 0x80000000u);
}
__device__ __forceinline__ float inv_key(unsigned k) {
    unsigned u = (k & 0x80000000u) ? (k ^ 0x80000000u) : ~k;
    return __uint_as_float(u);
}

__global__ __launch_bounds__(512) void attn_kernel(
    const float* __restrict__ Qg, const float* __restrict__ Kg,
    const float* __restrict__ Vg,
    float* __restrict__ Og)
{
    extern __shared__ char smraw[];
    AttnSmem4* sm = reinterpret_cast<AttnSmem4*>(smraw);

    int tile = blockIdx.x;           // b*1024 + h*128 + qt
    int qt = tile & 127;
    int h  = (tile >> 7) & 7;
    int b  = tile >> 10;
    int tid = threadIdx.x;

    int base_q = b * NQ + qt * QT;
    int base_k = b * NK;
    int hoff = h * DH;

    // stage q as row pairs: qp[p][d] = {q[2p][d], q[2p+1][d]}
    {
        int p = tid >> 6, d = tid & 63;   // 8 pairs x 64 dims = 512 entries
        const float* q0 = Qg + (size_t)(base_q + 2 * p)     * INNER + hoff;
        const float* q1 = Qg + (size_t)(base_q + 2 * p + 1) * INNER + hoff;
        sm->qp[p][d] = pk2(q0[d], q1[d]);
    }
    __syncthreads();

    int g  = tid >> 7;        // 0..3 -> q rows {4g .. 4g+3} (warp-uniform)
    int kl = tid & 127;       // k cols {kl, kl+128} in chunk
    int r0 = 4 * g;
    int p0 = 2 * g;           // row pairs p0 (rows 4g,4g+1) and p0+1 (rows 4g+2,4g+3)

    for (int c = 0; c < NCH; c++) {
        // cooperative K-chunk load: gmem coalesced (16 lanes span one K row),
        // stored dim-major for conflict-free compute reads
        {
            const float* src = Kg + (size_t)(base_k + c * CKC) * INNER + hoff;
            #pragma unroll
            for (int i = 0; i < 8; i++) {
                int e = tid + i * 512;
                int row = e >> 4, d4 = e & 15;
                sm->Ks4[d4][row] = *(const float4*)(src + (size_t)row * INNER + d4 * 4);
            }
        }
        __syncthreads();

        ull A00 = 0ull, A01 = 0ull, A10 = 0ull, A11 = 0ull;
        #pragma unroll
        for (int d4 = 0; d4 < 16; d4++) {
            float4 ka = sm->Ks4[d4][kl];              // lanes adjacent -> conflict-free
            float4 kb = sm->Ks4[d4][kl + 128];
            ull kax = pk2(ka.x, ka.x), kay = pk2(ka.y, ka.y);
            ull kaz = pk2(ka.z, ka.z), kaw = pk2(ka.w, ka.w);
            ull kbx = pk2(kb.x, kb.x), kby = pk2(kb.y, kb.y);
            ull kbz = pk2(kb.z, kb.z), kbw = pk2(kb.w, kb.w);
            ull qa0 = sm->qp[p0][d4 * 4 + 0];         // warp-uniform -> broadcast
            ull qa1 = sm->qp[p0][d4 * 4 + 1];
            ull qa2 = sm->qp[p0][d4 * 4 + 2];
            ull qa3 = sm->qp[p0][d4 * 4 + 3];
            ull qb0 = sm->qp[p0 + 1][d4 * 4 + 0];
            ull qb1 = sm->qp[p0 + 1][d4 * 4 + 1];
            ull qb2 = sm->qp[p0 + 1][d4 * 4 + 2];
            ull qb3 = sm->qp[p0 + 1][d4 * 4 + 3];
            // lane-lo = even row chain, lane-hi = odd row chain, d-ascending x..w
            A00 = fma2(qa0, kax, A00); A00 = fma2(qa1, kay, A00);
            A00 = fma2(qa2, kaz, A00); A00 = fma2(qa3, kaw, A00);
            A01 = fma2(qa0, kbx, A01); A01 = fma2(qa1, kby, A01);
            A01 = fma2(qa2, kbz, A01); A01 = fma2(qa3, kbw, A01);
            A10 = fma2(qb0, kax, A10); A10 = fma2(qb1, kay, A10);
            A10 = fma2(qb2, kaz, A10); A10 = fma2(qb3, kaw, A10);
            A11 = fma2(qb0, kbx, A11); A11 = fma2(qb1, kby, A11);
            A11 = fma2(qb2, kbz, A11); A11 = fma2(qb3, kbw, A11);
        }
        int kc = c * CKC;
        float v00, v01, v10, v11, v20, v21, v30, v31;
        upk2(A00, v00, v10);   // rows r0, r0+1 @ col kl
        upk2(A01, v01, v11);   // rows r0, r0+1 @ col kl+128
        upk2(A10, v20, v30);   // rows r0+2, r0+3 @ col kl
        upk2(A11, v21, v31);   // rows r0+2, r0+3 @ col kl+128
        sm->s[r0 + 0][kc + kl]       = v00 * 0.125f;
        sm->s[r0 + 0][kc + kl + 128] = v01 * 0.125f;
        sm->s[r0 + 1][kc + kl]       = v10 * 0.125f;
        sm->s[r0 + 1][kc + kl + 128] = v11 * 0.125f;
        sm->s[r0 + 2][kc + kl]       = v20 * 0.125f;
        sm->s[r0 + 2][kc + kl + 128] = v21 * 0.125f;
        sm->s[r0 + 3][kc + kl]       = v30 * 0.125f;
        sm->s[r0 + 3][kc + kl + 128] = v31 * 0.125f;
        __syncthreads();
    }

    // ---- per-warp exact radix select of the 64th-largest value ----
    const unsigned full = 0xFFFFFFFFu;
    int warp = tid >> 5, lane = tid & 31;
    int r = warp;                       // 16 warps == QT rows

    unsigned prefix = 0, pmask = 0;
    int krem = TOPKK;
    #pragma unroll
    for (int shift = 24; shift >= 0; shift -= 8) {
        for (int bi = lane; bi < 256; bi += 32) sm->hist[r][bi] = 0;
        __syncwarp();
        // vectorized scan: lane owns 4 consecutive elems per iter (LDS.128)
        #pragma unroll 4
        for (int i = 0; i < 16; i++) {
            int j = lane * 4 + i * 128;
            float4 sv = *(const float4*)&sm->s[r][j];
            unsigned u0 = key_of(sv.x), u1 = key_of(sv.y);
            unsigned u2 = key_of(sv.z), u3 = key_of(sv.w);
            bool b0p = ((u0 & pmask) == prefix);
            bool b1p = ((u1 & pmask) == prefix);
            bool b2p = ((u2 & pmask) == prefix);
            bool b3p = ((u3 & pmask) == prefix);
            if (b0p | b1p | b2p | b3p) {
                int b0 = (u0 >> shift) & 255;
                int b1 = (u1 >> shift) & 255;
                int b2 = (u2 >> shift) & 255;
                int b3 = (u3 >> shift) & 255;
                if (b0p & b1p & b2p & b3p & (b0 == b1) & (b0 == b2) & (b0 == b3)) {
                    atomicAdd(&sm->hist[r][b0], 4);
                } else {
                    if (b0p) atomicAdd(&sm->hist[r][b0], 1);
                    if (b1p) atomicAdd(&sm->hist[r][b1], 1);
                    if (b2p) atomicAdd(&sm->hist[r][b2], 1);
                    if (b3p) atomicAdd(&sm->hist[r][b3], 1);
                }
            }
        }
        __syncwarp();
        int basebin = 255 - 8 * lane;
        int gsum = 0;
        #pragma unroll
        for (int i = 0; i < 8; i++) gsum += sm->hist[r][basebin - i];
        int inc = gsum;
        #pragma unroll
        for (int off = 1; off < 32; off <<= 1) {
            int v = __shfl_up_sync(full, inc, off);
            if (lane >= off) inc += v;
        }
        int excl = inc - gsum;
        unsigned bal = __ballot_sync(full, (excl < krem) && (krem <= inc));
        int selLane = __ffs(bal) - 1;
        int exclSel = __shfl_sync(full, excl, selLane);
        int need = krem - exclSel;
        int gb = 255 - 8 * selLane;
        int selBin = -1, cc = 0, newNeed = 0;
        for (int i = 0; i < 8; i++) {
            int hh = sm->hist[r][gb - i];
            if (selBin < 0 && need <= cc + hh) { selBin = gb - i; newNeed = need - cc; }
            cc += hh;
        }
        krem = newNeed;
        prefix |= ((unsigned)selBin) << shift;
        pmask  |= (0xFFu << shift);
        __syncwarp();
    }
    float vkf = inv_key(prefix);

    // ---- vectorized deterministic gather of kept indices + row max ----
    int cbase = 0;
    float m = -FLT_MAX;
    unsigned ltm = (1u << lane) - 1u;
    #pragma unroll 4
    for (int i = 0; i < 16; i++) {
        int j = lane * 4 + i * 128;
        float4 sv = *(const float4*)&sm->s[r][j];
        bool k0 = (sv.x >= vkf), k1 = (sv.y >= vkf);
        bool k2 = (sv.z >= vkf), k3 = (sv.w >= vkf);
        unsigned b0 = __ballot_sync(full, k0);
        unsigned b1 = __ballot_sync(full, k1);
        unsigned b2 = __ballot_sync(full, k2);
        unsigned b3 = __ballot_sync(full, k3);
        m = fmaxf(m, fmaxf(fmaxf(sv.x, sv.y), fmaxf(sv.z, sv.w)));
        if (k0 | k1 | k2 | k3) {
            int pos = cbase + __popc(b0 & ltm) + __popc(b1 & ltm)
                            + __popc(b2 & ltm) + __popc(b3 & ltm);
            if (k0) { if (pos < CAP) sm->list[r][pos] = (unsigned short)j;       pos++; }
            if (k1) { if (pos < CAP) sm->list[r][pos] = (unsigned short)(j + 1); pos++; }
            if (k2) { if (pos < CAP) sm->list[r][pos] = (unsigned short)(j + 2); pos++; }
            if (k3) { if (pos < CAP) sm->list[r][pos] = (unsigned short)(j + 3); pos++; }
        }
        cbase += __popc(b0) + __popc(b1) + __popc(b2) + __popc(b3);
    }
    #pragma unroll
    for (int off = 16; off; off >>= 1) m = fmaxf(m, __shfl_xor_sync(full, m, off));
    if (lane == 0) sm->cnt[r] = cbase;
    __syncwarp();
    int n = sm->cnt[r];

    float acc0 = 0.f, acc1 = 0.f, sum = 0.f;
    const float* Vb = Vg + (size_t)base_k * INNER + hoff;

    if (n <= CAP) {
        float ls = 0.f;
        for (int e = lane; e < n; e += 32) {
            int j = sm->list[r][e];
            float p = expf(sm->s[r][j] - m);
            sm->plist[r][e] = p;
            ls += p;
        }
        #pragma unroll
        for (int off = 16; off; off >>= 1) ls += __shfl_xor_sync(full, ls, off);
        sum = ls;
        __syncwarp();
        #pragma unroll 4
        for (int e = 0; e < n; e++) {
            float p = sm->plist[r][e];
            int j = sm->list[r][e];
            const float* vp = Vb + (size_t)j * INNER;
            acc0 = fmaf(p, vp[lane],      acc0);
            acc1 = fmaf(p, vp[lane + 32], acc1);
        }
    } else {
        float ls = 0.f;
        for (int j = 0; j < NK; j++) {
            float sv = sm->s[r][j];
            if (sv >= vkf) {
                float p = expf(sv - m);
                ls += p;
                const float* vp = Vb + (size_t)j * INNER;
                acc0 = fmaf(p, vp[lane],      acc0);
                acc1 = fmaf(p, vp[lane + 32], acc1);
            }
        }
        sum = ls;
    }

    float invs = 1.0f / sum;
    float* op = Og + (size_t)(base_q + r) * INNER + hoff;
    op[lane]      = acc0 * invs;
    op[lane + 32] = acc1 * invs;
}

// ---------------- launch ----------------
extern "C" void kernel_launch(void* const* d_in, const int* in_sizes, int n_in,
                              void* d_out, int out_size)
{
    const float* x       = (const float*)d_in[0];
    const float* context = (const float*)d_in[1];
    // d_in[2]/d_in[3] are the bool masks; constant all-True in this problem.
    const float* Wq = (const float*)d_in[4];
    const float* bq = (const float*)d_in[5];
    const float* Wk = (const float*)d_in[6];
    const float* bk = (const float*)d_in[7];
    const float* Wv = (const float*)d_in[8];
    const float* bv = (const float*)d_in[9];
    const float* Wo = (const float*)d_in[10];
    const float* bo = (const float*)d_in[11];
    float* out = (float*)d_out;

    void *pAq, *pAk, *pQ, *pK, *pV, *pO;
    cudaGetSymbolAddress(&pAq, g_Aq);
    cudaGetSymbolAddress(&pAk, g_Ak);
    cudaGetSymbolAddress(&pQ,  g_Q);
    cudaGetSymbolAddress(&pK,  g_K);
    cudaGetSymbolAddress(&pV,  g_V);
    cudaGetSymbolAddress(&pO,  g_O);
    float* Aq = (float*)pAq; float* Ak = (float*)pAk;
    float* Qd = (float*)pQ;  float* Kd = (float*)pK;
    float* Vd = (float*)pV;  float* Od = (float*)pO;

    cudaFuncSetAttribute(attn_kernel, cudaFuncAttributeMaxDynamicSharedMemorySize,
                         (int)sizeof(AttnSmem4));

    enc_kernel<<<(NQ + 255) / 256, 256>>>();

    int tot = MROWS * DWP;
    concat_kernel<<<(tot + 255) / 256, 256>>>(x, context);

    dim3 gg(INNER / 64, MROWS / 128);   // (8, 32)
    gemm_bias<<<gg, 256>>>(Aq, DWP, Wq, bq, Qd, MROWS, INNER, DWP);
    gemm_bias<<<gg, 256>>>(Ak, DWP, Wk, bk, Kd, MROWS, INNER, DWP);
    gemm_bias<<<gg, 256>>>(context, DIMM, Wv, bv, Vd, MROWS, INNER, DIMM);

    attn_kernel<<<BB * HH * (NQ / QT), 512, sizeof(AttnSmem4)>>>(Qd, Kd, Vd, Od);

    gemm_bias<<<gg, 256>>>(Od, INNER, Wo, bo, out, MROWS, DIMM, INNER);
}